// round 7
// baseline (speedup 1.0000x reference)
#include <cuda_runtime.h>
#include <cuda_bf16.h>
#include <mma.h>
#include <math.h>

using namespace nvcuda;

// ---------------------------------------------------------------------------
// Problem constants
// ---------------------------------------------------------------------------
#define T_TOK  1024
#define HID    1024
#define NH     16
#define NKV    4
#define HD     64
#define QKV_N  1536
#define NE     64
#define NG     8
#define INTER  512
#define NA     (T_TOK*NG)
#define NA_PAD 16384

// GEMM tiling
#define BM 128
#define BN 128
#define BK 32
#define LDA_S 40
#define LDB_S 136
#define NST 3

// attention smem leading dim
#define LDH 72

// ---------------------------------------------------------------------------
// Scratch (static device globals)
// ---------------------------------------------------------------------------
__device__ __nv_bfloat16 g_hb   [T_TOK*HID];
__device__ float         g_qkv  [T_TOK*QKV_N];
__device__ __nv_bfloat16 g_qb   [T_TOK*NH*HD];
__device__ __nv_bfloat16 g_kb   [T_TOK*NKV*HD];
__device__ __nv_bfloat16 g_vb   [T_TOK*NKV*HD];
__device__ __nv_bfloat16 g_attnb[T_TOK*NH*HD];
__device__ float         g_h2   [T_TOK*HID];
__device__ __nv_bfloat16 g_h2b  [T_TOK*HID];
__device__ __nv_bfloat16 g_actb [NA_PAD*INTER];
__device__ int   g_cnt [NE];
__device__ int   g_off [NE];
__device__ int   g_fill[NE];
__device__ int   g_total;
__device__ int   g_selid[NA];
__device__ float g_selw [NA];
__device__ int   g_tok  [NA_PAD];
__device__ float g_w    [NA_PAD];
// bf16 weight mirrors (converted each launch)
__device__ __nv_bfloat16 g_wqkvb[HID*QKV_N];
__device__ __nv_bfloat16 g_wob  [NH*HD*HID];
__device__ __nv_bfloat16 g_wgub [NE*HID*1024];
__device__ __nv_bfloat16 g_wdb  [NE*INTER*HID];

// ---------------------------------------------------------------------------
// WMMA types + async copy helpers
// ---------------------------------------------------------------------------
using FragA  = wmma::fragment<wmma::matrix_a, 16, 16, 16, __nv_bfloat16, wmma::row_major>;
using FragB  = wmma::fragment<wmma::matrix_b, 16, 16, 16, __nv_bfloat16, wmma::row_major>;
using FragBc = wmma::fragment<wmma::matrix_b, 16, 16, 16, __nv_bfloat16, wmma::col_major>;
using FragC  = wmma::fragment<wmma::accumulator, 16, 16, 16, float>;

__device__ __forceinline__ void cp16(unsigned dst, const void* src) {
    asm volatile("cp.async.cg.shared.global [%0], [%1], 16;\n" :: "r"(dst), "l"(src));
}
__device__ __forceinline__ void cp16z(unsigned dst, const void* src, int valid) {
    asm volatile("cp.async.cg.shared.global [%0], [%1], 16, %2;\n"
                 :: "r"(dst), "l"(src), "r"(valid ? 16 : 0));
}
#define CP_COMMIT() asm volatile("cp.async.commit_group;\n")
template<int N> __device__ __forceinline__ void cp_wait() {
    asm volatile("cp.async.wait_group %0;\n" :: "n"(N));
}

__device__ __forceinline__ uint4 f8_to_bf8(float4 a, float4 b) {
    __nv_bfloat162 p0 = __floats2bfloat162_rn(a.x, a.y);
    __nv_bfloat162 p1 = __floats2bfloat162_rn(a.z, a.w);
    __nv_bfloat162 p2 = __floats2bfloat162_rn(b.x, b.y);
    __nv_bfloat162 p3 = __floats2bfloat162_rn(b.z, b.w);
    uint4 r;
    r.x = *reinterpret_cast<unsigned*>(&p0);
    r.y = *reinterpret_cast<unsigned*>(&p1);
    r.z = *reinterpret_cast<unsigned*>(&p2);
    r.w = *reinterpret_cast<unsigned*>(&p3);
    return r;
}

__device__ __forceinline__ void mma_tile(const __nv_bfloat16* As, const __nv_bfloat16* Bs,
                                         FragC (&acc)[2][4], int wm, int wn) {
#pragma unroll
    for (int kk = 0; kk < BK; kk += 16) {
        FragA a[2];
        FragB b[4];
#pragma unroll
        for (int i = 0; i < 2; i++)
            wmma::load_matrix_sync(a[i], As + (wm * 32 + i * 16) * LDA_S + kk, LDA_S);
#pragma unroll
        for (int j = 0; j < 4; j++)
            wmma::load_matrix_sync(b[j], Bs + kk * LDB_S + wn * 64 + j * 16, LDB_S);
#pragma unroll
        for (int i = 0; i < 2; i++)
#pragma unroll
            for (int j = 0; j < 4; j++)
                wmma::mma_sync(acc[i][j], a[i], b[j], acc[i][j]);
    }
}

// raw PTX mma/ldmatrix for attention
__device__ __forceinline__ void mma16816(float c[4], const unsigned a[4],
                                         unsigned b0, unsigned b1) {
    asm volatile(
        "mma.sync.aligned.m16n8k16.row.col.f32.bf16.bf16.f32 "
        "{%0,%1,%2,%3}, {%4,%5,%6,%7}, {%8,%9}, {%0,%1,%2,%3};\n"
        : "+f"(c[0]), "+f"(c[1]), "+f"(c[2]), "+f"(c[3])
        : "r"(a[0]), "r"(a[1]), "r"(a[2]), "r"(a[3]), "r"(b0), "r"(b1));
}
__device__ __forceinline__ void ldsm4(unsigned d[4], unsigned addr) {
    asm volatile("ldmatrix.sync.aligned.m8n8.x4.shared.b16 {%0,%1,%2,%3}, [%4];\n"
        : "=r"(d[0]), "=r"(d[1]), "=r"(d[2]), "=r"(d[3]) : "r"(addr));
}
__device__ __forceinline__ void ldsm4t(unsigned d[4], unsigned addr) {
    asm volatile("ldmatrix.sync.aligned.m8n8.x4.trans.shared.b16 {%0,%1,%2,%3}, [%4];\n"
        : "=r"(d[0]), "=r"(d[1]), "=r"(d[2]), "=r"(d[3]) : "r"(addr));
}

// ---------------------------------------------------------------------------
// fp32 -> bf16 streaming conversion (8 elems / thread)
// ---------------------------------------------------------------------------
__global__ void k_f2b(const float* __restrict__ s, __nv_bfloat16* __restrict__ d, int n8) {
    int i = blockIdx.x * 256 + threadIdx.x;
    if (i >= n8) return;
    const float4* p = (const float4*)s + (size_t)i * 2;
    float4 a = p[0], b = p[1];
    *((uint4*)d + i) = f8_to_bf8(a, b);
}

// ---------------------------------------------------------------------------
// RMSNorm
// ---------------------------------------------------------------------------
__global__ void k_rmsnorm(const float* __restrict__ in,
                          const float* __restrict__ w,
                          float* __restrict__ outf,
                          __nv_bfloat16* __restrict__ outb) {
    int t = blockIdx.x;
    const float* x = in + (size_t)t * HID;
    float ss = 0.f;
    for (int i = threadIdx.x; i < HID; i += 256) { float v = x[i]; ss += v * v; }
#pragma unroll
    for (int o = 16; o; o >>= 1) ss += __shfl_xor_sync(0xffffffffu, ss, o);
    __shared__ float red[8];
    __shared__ float stot;
    if ((threadIdx.x & 31) == 0) red[threadIdx.x >> 5] = ss;
    __syncthreads();
    if (threadIdx.x == 0) {
        float s = 0.f;
#pragma unroll
        for (int i = 0; i < 8; i++) s += red[i];
        stot = rsqrtf(s * (1.f / HID) + 1e-6f);
    }
    __syncthreads();
    float sc = stot;
    for (int i = threadIdx.x; i < HID; i += 256) {
        float v = x[i] * sc * w[i];
        if (outf) outf[(size_t)t * HID + i] = v;
        if (outb) outb[(size_t)t * HID + i] = __float2bfloat16(v);
    }
}

// ---------------------------------------------------------------------------
// Dense bf16 GEMM, 3-stage cp.async pipeline (A bf16, B bf16)
// ---------------------------------------------------------------------------
__global__ void __launch_bounds__(256) k_gemm_bb(
        const __nv_bfloat16* __restrict__ A, const __nv_bfloat16* __restrict__ B,
        float* __restrict__ C, const float* __restrict__ R,
        int M, int N, int K) {
    __shared__ __nv_bfloat16 As[NST][BM * LDA_S];
    __shared__ __nv_bfloat16 Bs[NST][BK * LDB_S];
    int tid = threadIdx.x;
    int warp = tid >> 5;
    int wm = warp & 3, wn = warp >> 2;
    int m0 = blockIdx.y * BM, n0 = blockIdx.x * BN;

    int ar = tid >> 2, ac = (tid & 3) * 8;      // rows ar, ar+64
    int br = tid >> 4, bc = (tid & 15) * 8;     // rows br, br+16
    const __nv_bfloat16* a0 = A + (size_t)(m0 + ar) * K + ac;
    const __nv_bfloat16* a1 = A + (size_t)(m0 + ar + 64) * K + ac;
    const __nv_bfloat16* b0 = B + (size_t)br * N + n0 + bc;
    const __nv_bfloat16* b1 = B + (size_t)(br + 16) * N + n0 + bc;
    unsigned dA0 = (unsigned)__cvta_generic_to_shared(&As[0][ar * LDA_S + ac]);
    unsigned dA1 = (unsigned)__cvta_generic_to_shared(&As[0][(ar + 64) * LDA_S + ac]);
    unsigned dB0 = (unsigned)__cvta_generic_to_shared(&Bs[0][br * LDB_S + bc]);
    unsigned dB1 = (unsigned)__cvta_generic_to_shared(&Bs[0][(br + 16) * LDB_S + bc]);
    const unsigned szA = BM * LDA_S * 2, szB = BK * LDB_S * 2;

    FragC acc[2][4];
    if (R) {
#pragma unroll
        for (int i = 0; i < 2; i++)
#pragma unroll
            for (int j = 0; j < 4; j++)
                wmma::load_matrix_sync(acc[i][j],
                    R + (size_t)(m0 + wm * 32 + i * 16) * N + n0 + wn * 64 + j * 16,
                    N, wmma::mem_row_major);
    } else {
#pragma unroll
        for (int i = 0; i < 2; i++)
#pragma unroll
            for (int j = 0; j < 4; j++) wmma::fill_fragment(acc[i][j], 0.f);
    }

    auto cpS = [&](int st, int k0) {
        cp16(dA0 + st * szA, a0 + k0);
        cp16(dA1 + st * szA, a1 + k0);
        cp16(dB0 + st * szB, b0 + (size_t)k0 * N);
        cp16(dB1 + st * szB, b1 + (size_t)k0 * N);
    };

    const int niter = K / BK;
    cpS(0, 0); CP_COMMIT();
    cpS(1, BK); CP_COMMIT();
    cp_wait<1>(); __syncthreads();
    int sc = 0;
    for (int it = 0; it < niter; it++) {
        mma_tile(As[sc], Bs[sc], acc, wm, wn);
        if (it + 2 < niter) {
            int sp = sc + 2 >= NST ? sc + 2 - NST : sc + 2;
            cpS(sp, (it + 2) * BK); CP_COMMIT();
            cp_wait<1>();
        } else cp_wait<0>();
        __syncthreads();
        sc = (sc + 1 == NST) ? 0 : sc + 1;
    }
#pragma unroll
    for (int i = 0; i < 2; i++)
#pragma unroll
        for (int j = 0; j < 4; j++)
            wmma::store_matrix_sync(
                C + (size_t)(m0 + wm * 32 + i * 16) * N + n0 + wn * 64 + j * 16,
                acc[i][j], N, wmma::mem_row_major);
}

// ---------------------------------------------------------------------------
// Per-head RMSNorm + RoPE (q,k) and copy (v) -> bf16
// ---------------------------------------------------------------------------
__global__ void k_qk_prep(const int* __restrict__ pos,
                          const float* __restrict__ qnw,
                          const float* __restrict__ knw) {
    int hh = blockIdx.x;
    int t  = blockIdx.y;
    int i  = threadIdx.x;
    if (hh >= NH + NKV) {
        int vh = hh - NH - NKV;
        const float* src = g_qkv + (size_t)t * QKV_N + (NH + NKV) * HD + vh * HD;
        __nv_bfloat16* dst = g_vb + (size_t)t * (NKV * HD) + vh * HD;
        dst[i]      = __float2bfloat16(src[i]);
        dst[i + 32] = __float2bfloat16(src[i + 32]);
        return;
    }
    const float* src; __nv_bfloat16* dst; const float* w;
    if (hh < NH) {
        src = g_qkv + (size_t)t * QKV_N + hh * HD;
        dst = g_qb  + (size_t)t * (NH * HD) + hh * HD;
        w = qnw;
    } else {
        int kh = hh - NH;
        src = g_qkv + (size_t)t * QKV_N + NH * HD + kh * HD;
        dst = g_kb  + (size_t)t * (NKV * HD) + kh * HD;
        w = knw;
    }
    float x1 = src[i], x2 = src[i + 32];
    float ss = x1 * x1 + x2 * x2;
#pragma unroll
    for (int o = 16; o; o >>= 1) ss += __shfl_xor_sync(0xffffffffu, ss, o);
    float sc = rsqrtf(ss * (1.f / 64.f) + 1e-6f);
    x1 *= sc * w[i];
    x2 *= sc * w[i + 32];
    float p = (float)pos[t];
    float inv = powf(10000.f, -(float)i * (1.f / 32.f));
    float f = p * inv;
    float c = cosf(f), s = sinf(f);
    dst[i]      = __float2bfloat16(x1 * c - x2 * s);
    dst[i + 32] = __float2bfloat16(x2 * c + x1 * s);
}

// ---------------------------------------------------------------------------
// Flash attention (round-6 register-resident FA2, unchanged)
// ---------------------------------------------------------------------------
__global__ void __launch_bounds__(128) k_attn_mma() {
    __shared__ __nv_bfloat16 Qs[64 * LDH];
    __shared__ __nv_bfloat16 Ks[64 * LDH];
    __shared__ __nv_bfloat16 Vs[64 * LDH];
    int h = blockIdx.y, qt = blockIdx.x;
    int m0 = qt * 64, kvh = h >> 2;
    int tid = threadIdx.x, warp = tid >> 5, lane = tid & 31;
    int g = lane >> 3, li = lane & 7;

#pragma unroll
    for (int j = 0; j < 4; j++) {
        int idx = tid + j * 128;
        int r = idx >> 3, c = (idx & 7) * 8;
        *(uint4*)&Qs[r * LDH + c] =
            *(const uint4*)&g_qb[(size_t)(m0 + r) * (NH * HD) + h * HD + c];
    }
    __syncthreads();

    unsigned qa[4][4];
    {
        int row = warp * 16 + (g & 1) * 8 + li;
        int colg = (g >> 1) * 8;
#pragma unroll
        for (int hc = 0; hc < 4; hc++)
            ldsm4(qa[hc], (unsigned)__cvta_generic_to_shared(&Qs[row * LDH + hc * 16 + colg]));
    }

    float o[8][4];
#pragma unroll
    for (int f = 0; f < 8; f++) { o[f][0] = o[f][1] = o[f][2] = o[f][3] = 0.f; }
    float mr0 = -INFINITY, mr1 = -INFINITY, l0 = 0.f, l1 = 0.f;
    int R0 = m0 + warp * 16 + (lane >> 2);
    int R1 = R0 + 8;

    for (int nt = 0; nt <= qt; nt++) {
        int n0 = nt * 64;
        __syncthreads();
#pragma unroll
        for (int j = 0; j < 4; j++) {
            int idx = tid + j * 128;
            int r = idx >> 3, c = (idx & 7) * 8;
            *(uint4*)&Ks[r * LDH + c] =
                *(const uint4*)&g_kb[(size_t)(n0 + r) * (NKV * HD) + kvh * HD + c];
            *(uint4*)&Vs[r * LDH + c] =
                *(const uint4*)&g_vb[(size_t)(n0 + r) * (NKV * HD) + kvh * HD + c];
        }
        __syncthreads();

        float s[8][4];
#pragma unroll
        for (int f = 0; f < 8; f++) { s[f][0] = s[f][1] = s[f][2] = s[f][3] = 0.f; }
#pragma unroll
        for (int hc = 0; hc < 4; hc++) {
#pragma unroll
            for (int ng = 0; ng < 4; ng++) {
                unsigned d[4];
                int row = ng * 16 + (g >> 1) * 8 + li;
                int col = hc * 16 + (g & 1) * 8;
                ldsm4(d, (unsigned)__cvta_generic_to_shared(&Ks[row * LDH + col]));
                mma16816(s[2 * ng],     qa[hc], d[0], d[1]);
                mma16816(s[2 * ng + 1], qa[hc], d[2], d[3]);
            }
        }

        bool diag = (nt == qt);
        float mx0 = -INFINITY, mx1 = -INFINITY;
#pragma unroll
        for (int f = 0; f < 8; f++) {
            int cb = n0 + f * 8 + (lane & 3) * 2;
            s[f][0] *= 0.125f; s[f][1] *= 0.125f;
            s[f][2] *= 0.125f; s[f][3] *= 0.125f;
            if (diag) {
                if (cb     > R0) s[f][0] = -INFINITY;
                if (cb + 1 > R0) s[f][1] = -INFINITY;
                if (cb     > R1) s[f][2] = -INFINITY;
                if (cb + 1 > R1) s[f][3] = -INFINITY;
            }
            mx0 = fmaxf(mx0, fmaxf(s[f][0], s[f][1]));
            mx1 = fmaxf(mx1, fmaxf(s[f][2], s[f][3]));
        }
        mx0 = fmaxf(mx0, __shfl_xor_sync(0xffffffffu, mx0, 1));
        mx0 = fmaxf(mx0, __shfl_xor_sync(0xffffffffu, mx0, 2));
        mx1 = fmaxf(mx1, __shfl_xor_sync(0xffffffffu, mx1, 1));
        mx1 = fmaxf(mx1, __shfl_xor_sync(0xffffffffu, mx1, 2));
        float mn0 = fmaxf(mr0, mx0), mn1 = fmaxf(mr1, mx1);
        float al0 = __expf(mr0 - mn0), al1 = __expf(mr1 - mn1);
        mr0 = mn0; mr1 = mn1;

        unsigned P[4][4];
        float ps0 = 0.f, ps1 = 0.f;
#pragma unroll
        for (int f = 0; f < 8; f++) {
            float p0 = __expf(s[f][0] - mn0);
            float p1 = __expf(s[f][1] - mn0);
            float p2 = __expf(s[f][2] - mn1);
            float p3 = __expf(s[f][3] - mn1);
            ps0 += p0 + p1; ps1 += p2 + p3;
            __nv_bfloat162 b0 = __floats2bfloat162_rn(p0, p1);
            __nv_bfloat162 b1 = __floats2bfloat162_rn(p2, p3);
            P[f >> 1][(f & 1) * 2]     = *reinterpret_cast<unsigned*>(&b0);
            P[f >> 1][(f & 1) * 2 + 1] = *reinterpret_cast<unsigned*>(&b1);
        }
        ps0 += __shfl_xor_sync(0xffffffffu, ps0, 1);
        ps0 += __shfl_xor_sync(0xffffffffu, ps0, 2);
        ps1 += __shfl_xor_sync(0xffffffffu, ps1, 1);
        ps1 += __shfl_xor_sync(0xffffffffu, ps1, 2);
        l0 = l0 * al0 + ps0;
        l1 = l1 * al1 + ps1;
#pragma unroll
        for (int f = 0; f < 8; f++) {
            o[f][0] *= al0; o[f][1] *= al0;
            o[f][2] *= al1; o[f][3] *= al1;
        }

#pragma unroll
        for (int c = 0; c < 4; c++) {
#pragma unroll
            for (int j = 0; j < 4; j++) {
                unsigned d[4];
                int row = c * 16 + (g & 1) * 8 + li;
                int col = j * 16 + (g >> 1) * 8;
                ldsm4t(d, (unsigned)__cvta_generic_to_shared(&Vs[row * LDH + col]));
                mma16816(o[2 * j],     P[c], d[0], d[1]);
                mma16816(o[2 * j + 1], P[c], d[2], d[3]);
            }
        }
    }

    float i0 = 1.f / l0, i1 = 1.f / l1;
#pragma unroll
    for (int f = 0; f < 8; f++) {
        int col = h * HD + f * 8 + (lane & 3) * 2;
        __nv_bfloat162 v0 = __floats2bfloat162_rn(o[f][0] * i0, o[f][1] * i0);
        __nv_bfloat162 v1 = __floats2bfloat162_rn(o[f][2] * i1, o[f][3] * i1);
        *(unsigned*)&g_attnb[(size_t)R0 * (NH * HD) + col] = *reinterpret_cast<unsigned*>(&v0);
        *(unsigned*)&g_attnb[(size_t)R1 * (NH * HD) + col] = *reinterpret_cast<unsigned*>(&v1);
    }
}

// ---------------------------------------------------------------------------
// Routing
// ---------------------------------------------------------------------------
__global__ void k_zero() {
    int i = threadIdx.x;
    if (i < NE) { g_cnt[i] = 0; g_fill[i] = 0; }
}

__global__ void k_route(const float* __restrict__ H2, const float* __restrict__ Wg) {
    int t = blockIdx.x;
    int e = threadIdx.x;
    __shared__ float sh[HID];
    for (int i = e; i < HID; i += 64) sh[i] = H2[(size_t)t * HID + i];
    __syncthreads();
    float a0 = 0, a1 = 0, a2 = 0, a3 = 0;
    for (int k = 0; k < HID; k += 4) {
        a0 += sh[k]     * Wg[(size_t)k       * NE + e];
        a1 += sh[k + 1] * Wg[(size_t)(k + 1) * NE + e];
        a2 += sh[k + 2] * Wg[(size_t)(k + 2) * NE + e];
        a3 += sh[k + 3] * Wg[(size_t)(k + 3) * NE + e];
    }
    __shared__ float logits[NE];
    logits[e] = (a0 + a1) + (a2 + a3);
    __syncthreads();
    if (e == 0) {
        float sv[NG]; int si[NG];
#pragma unroll
        for (int gg = 0; gg < NG; gg++) {
            float best = logits[gg * 8]; int bi = gg * 8;
#pragma unroll
            for (int j = 1; j < 8; j++) {
                float v = logits[gg * 8 + j];
                if (v > best) { best = v; bi = gg * 8 + j; }
            }
            sv[gg] = best; si[gg] = bi;
        }
        float m = sv[0];
#pragma unroll
        for (int gg = 1; gg < NG; gg++) m = fmaxf(m, sv[gg]);
        float sum = 0.f, p[NG];
#pragma unroll
        for (int gg = 0; gg < NG; gg++) { p[gg] = expf(sv[gg] - m); sum += p[gg]; }
        float is = 1.f / sum;
#pragma unroll
        for (int gg = 0; gg < NG; gg++) {
            g_selid[t * NG + gg] = si[gg];
            g_selw [t * NG + gg] = p[gg] * is;
            atomicAdd(&g_cnt[si[gg]], 1);
        }
    }
}

__global__ void k_scan() {
    int s = 0;
    for (int e = 0; e < NE; e++) { g_off[e] = s; s += (g_cnt[e] + BM - 1) & ~(BM - 1); }
    g_total = s;
}

__global__ void k_scatter() {
    int t = blockIdx.x, gg = threadIdx.x;
    int e = g_selid[t * NG + gg];
    int slot = atomicAdd(&g_fill[e], 1);
    int row = g_off[e] + slot;
    g_tok[row] = t;
    g_w[row]   = g_selw[t * NG + gg];
}

// ---------------------------------------------------------------------------
// MoE GEMM 1 + fused activation epilogue.
// Block tile: 128 rows x (64 gate cols + 64 up cols). 3-stage cp.async.
// Epilogue stages C in smem (aliasing the pipeline buffers) and writes
// silu(g)*u*w as bf16 straight to g_actb. No g_gu buffer, no act kernel.
// ---------------------------------------------------------------------------
#define MOE1_SMEM (128*132*4)   // 67584 >= pipeline (56832)
__global__ void __launch_bounds__(256) k_moe1(const __nv_bfloat16* __restrict__ Ab,
                                              const __nv_bfloat16* __restrict__ Bw) {
    __shared__ __align__(16) char sraw[MOE1_SMEM];
    __shared__ int stok[BM];
    __nv_bfloat16* As = (__nv_bfloat16*)sraw;               // NST stages
    __nv_bfloat16* Bs = As + NST * BM * LDA_S;
    float* Ebuf = (float*)sraw;                             // epilogue alias

    int e = blockIdx.z;
    int cnt = g_cnt[e];
    int m0 = blockIdx.y * BM;
    if (m0 >= cnt) return;
    int off = g_off[e];
    int n0 = blockIdx.x * 64;                               // intermediate col base
    const __nv_bfloat16* B = Bw + (size_t)e * (HID * 1024);

    int tid = threadIdx.x;
    int warp = tid >> 5;
    int wm = warp & 3, wn = warp >> 2;
    if (tid < BM) stok[tid] = (m0 + tid < cnt) ? g_tok[off + m0 + tid] : -1;
    __syncthreads();

    int ar = tid >> 2, ac = (tid & 3) * 8;
    int br = tid >> 4, bc = (tid & 15) * 8;
    int tk0 = stok[ar], tk1 = stok[ar + 64];
    const __nv_bfloat16* a0 = Ab + (size_t)((tk0 >= 0) ? tk0 : 0) * HID + ac;
    const __nv_bfloat16* a1 = Ab + (size_t)((tk1 >= 0) ? tk1 : 0) * HID + ac;
    int colg = (bc < 64) ? (n0 + bc) : (512 + n0 + bc - 64); // gate | up columns
    const __nv_bfloat16* b0 = B + (size_t)br * 1024 + colg;
    const __nv_bfloat16* b1 = B + (size_t)(br + 16) * 1024 + colg;
    unsigned dA0 = (unsigned)__cvta_generic_to_shared(&As[ar * LDA_S + ac]);
    unsigned dA1 = (unsigned)__cvta_generic_to_shared(&As[(ar + 64) * LDA_S + ac]);
    unsigned dB0 = (unsigned)__cvta_generic_to_shared(&Bs[br * LDB_S + bc]);
    unsigned dB1 = (unsigned)__cvta_generic_to_shared(&Bs[(br + 16) * LDB_S + bc]);
    const unsigned szA = BM * LDA_S * 2, szB = BK * LDB_S * 2;

    FragC acc[2][4];
#pragma unroll
    for (int i = 0; i < 2; i++)
#pragma unroll
        for (int j = 0; j < 4; j++) wmma::fill_fragment(acc[i][j], 0.f);

    auto cpS = [&](int st, int k0) {
        cp16z(dA0 + st * szA, a0 + k0, tk0 >= 0);
        cp16z(dA1 + st * szA, a1 + k0, tk1 >= 0);
        cp16(dB0 + st * szB, b0 + (size_t)k0 * 1024);
        cp16(dB1 + st * szB, b1 + (size_t)k0 * 1024);
    };

    const int niter = HID / BK;
    cpS(0, 0); CP_COMMIT();
    cpS(1, BK); CP_COMMIT();
    cp_wait<1>(); __syncthreads();
    int sc = 0;
    for (int it = 0; it < niter; it++) {
        mma_tile(As + sc * BM * LDA_S, Bs + sc * BK * LDB_S, acc, wm, wn);
        if (it + 2 < niter) {
            int sp = sc + 2 >= NST ? sc + 2 - NST : sc + 2;
            cpS(sp, (it + 2) * BK); CP_COMMIT();
            cp_wait<1>();
        } else cp_wait<0>();
        __syncthreads();
        sc = (sc + 1 == NST) ? 0 : sc + 1;
    }

    // ---- fused activation epilogue ----
    // stage full C tile (128 x 128 fp32) into Ebuf (aliases pipeline smem)
#pragma unroll
    for (int i = 0; i < 2; i++)
#pragma unroll
        for (int j = 0; j < 4; j++)
            wmma::store_matrix_sync(Ebuf + (wm * 32 + i * 16) * 132 + wn * 64 + j * 16,
                                    acc[i][j], 132, wmma::mem_row_major);
    __syncthreads();

    int r  = tid >> 1;
    int c0 = (tid & 1) * 32;
    float w = g_w[off + m0 + r];
#pragma unroll
    for (int c = 0; c < 32; c += 4) {
        float4 gv = *(float4*)&Ebuf[r * 132 + c0 + c];
        float4 uv = *(float4*)&Ebuf[r * 132 + 64 + c0 + c];
        float s0 = gv.x / (1.f + __expf(-gv.x)) * uv.x * w;
        float s1 = gv.y / (1.f + __expf(-gv.y)) * uv.y * w;
        float s2 = gv.z / (1.f + __expf(-gv.z)) * uv.z * w;
        float s3 = gv.w / (1.f + __expf(-gv.w)) * uv.w * w;
        __nv_bfloat162 p0 = __floats2bfloat162_rn(s0, s1);
        __nv_bfloat162 p1 = __floats2bfloat162_rn(s2, s3);
        uint2 v;
        v.x = *reinterpret_cast<unsigned*>(&p0);
        v.y = *reinterpret_cast<unsigned*>(&p1);
        *(uint2*)&g_actb[(size_t)(off + m0 + r) * INTER + n0 + c0 + c] = v;
    }
}

// ---------------------------------------------------------------------------
// MoE GEMM 2: out[tok] += act @ Wd[e]. 3-stage cp.async, staged scatter-add.
// ---------------------------------------------------------------------------
__global__ void __launch_bounds__(256) k_moe2(const __nv_bfloat16* __restrict__ Bw,
                                              float* __restrict__ out) {
    __shared__ __nv_bfloat16 As[NST][BM * LDA_S];
    __shared__ __nv_bfloat16 Bs[NST][BK * LDB_S];
    __shared__ float stage_s[8 * 272];
    __shared__ int stok[BM];

    int e = blockIdx.z;
    int cnt = g_cnt[e];
    int m0 = blockIdx.y * BM;
    if (m0 >= cnt) return;
    int off = g_off[e];
    int n0 = blockIdx.x * BN;
    const __nv_bfloat16* B = Bw + (size_t)e * (INTER * HID);

    int tid = threadIdx.x;
    int lane = tid & 31;
    int warp = tid >> 5;
    int wm = warp & 3, wn = warp >> 2;
    if (tid < BM) stok[tid] = (m0 + tid < cnt) ? g_tok[off + m0 + tid] : -1;
    __syncthreads();

    int ar = tid >> 2, ac = (tid & 3) * 8;
    int br = tid >> 4, bc = (tid & 15) * 8;
    const __nv_bfloat16* a0 = g_actb + (size_t)(off + m0 + ar) * INTER + ac;
    const __nv_bfloat16* a1 = g_actb + (size_t)(off + m0 + ar + 64) * INTER + ac;
    const __nv_bfloat16* b0 = B + (size_t)br * HID + n0 + bc;
    const __nv_bfloat16* b1 = B + (size_t)(br + 16) * HID + n0 + bc;
    unsigned dA0 = (unsigned)__cvta_generic_to_shared(&As[0][ar * LDA_S + ac]);
    unsigned dA1 = (unsigned)__cvta_generic_to_shared(&As[0][(ar + 64) * LDA_S + ac]);
    unsigned dB0 = (unsigned)__cvta_generic_to_shared(&Bs[0][br * LDB_S + bc]);
    unsigned dB1 = (unsigned)__cvta_generic_to_shared(&Bs[0][(br + 16) * LDB_S + bc]);
    const unsigned szA = BM * LDA_S * 2, szB = BK * LDB_S * 2;

    FragC acc[2][4];
#pragma unroll
    for (int i = 0; i < 2; i++)
#pragma unroll
        for (int j = 0; j < 4; j++) wmma::fill_fragment(acc[i][j], 0.f);

    auto cpS = [&](int st, int k0) {
        cp16(dA0 + st * szA, a0 + k0);
        cp16(dA1 + st * szA, a1 + k0);
        cp16(dB0 + st * szB, b0 + (size_t)k0 * HID);
        cp16(dB1 + st * szB, b1 + (size_t)k0 * HID);
    };

    const int niter = INTER / BK;
    cpS(0, 0); CP_COMMIT();
    cpS(1, BK); CP_COMMIT();
    cp_wait<1>(); __syncthreads();
    int sc = 0;
    for (int it = 0; it < niter; it++) {
        mma_tile(As[sc], Bs[sc], acc, wm, wn);
        if (it + 2 < niter) {
            int sp = sc + 2 >= NST ? sc + 2 - NST : sc + 2;
            cpS(sp, (it + 2) * BK); CP_COMMIT();
            cp_wait<1>();
        } else cp_wait<0>();
        __syncthreads();
        sc = (sc + 1 == NST) ? 0 : sc + 1;
    }

#pragma unroll
    for (int i = 0; i < 2; i++) {
#pragma unroll
        for (int j = 0; j < 4; j++) {
            wmma::store_matrix_sync(&stage_s[warp * 272], acc[i][j], 16, wmma::mem_row_major);
            __syncwarp();
#pragma unroll
            for (int q = 0; q < 8; q++) {
                int el = lane + q * 32;
                int r = el >> 4, c = el & 15;
                int lr = wm * 32 + i * 16 + r;
                if (m0 + lr < cnt) {
                    int tk = stok[lr];
                    atomicAdd(&out[(size_t)tk * HID + n0 + wn * 64 + j * 16 + c],
                              stage_s[warp * 272 + r * 16 + c]);
                }
            }
            __syncwarp();
        }
    }
}

// ---------------------------------------------------------------------------
// Launch
// ---------------------------------------------------------------------------
extern "C" void kernel_launch(void* const* d_in, const int* in_sizes, int n_in,
                              void* d_out, int out_size) {
    const int*   positions = (const int*)  d_in[0];
    const float* hidden    = (const float*)d_in[1];
    const float* Wqkv      = (const float*)d_in[2];
    const float* Wo        = (const float*)d_in[3];
    const float* qnw       = (const float*)d_in[4];
    const float* knw       = (const float*)d_in[5];
    const float* inln      = (const float*)d_in[6];
    const float* postln    = (const float*)d_in[7];
    const float* Wg        = (const float*)d_in[8];
    const float* Wgu       = (const float*)d_in[9];
    const float* Wd        = (const float*)d_in[10];
    float* out = (float*)d_out;

    __nv_bfloat16 *p_hb, *p_attnb, *p_h2b, *p_wqkvb, *p_wob, *p_wgub, *p_wdb;
    float *p_qkv, *p_h2;
    cudaGetSymbolAddress((void**)&p_hb,    g_hb);
    cudaGetSymbolAddress((void**)&p_qkv,   g_qkv);
    cudaGetSymbolAddress((void**)&p_h2,    g_h2);
    cudaGetSymbolAddress((void**)&p_h2b,   g_h2b);
    cudaGetSymbolAddress((void**)&p_attnb, g_attnb);
    cudaGetSymbolAddress((void**)&p_wqkvb, g_wqkvb);
    cudaGetSymbolAddress((void**)&p_wob,   g_wob);
    cudaGetSymbolAddress((void**)&p_wgub,  g_wgub);
    cudaGetSymbolAddress((void**)&p_wdb,   g_wdb);

    // 0. weight conversions fp32 -> bf16
    k_f2b<<<(HID * QKV_N / 8 + 255) / 256, 256>>>(Wqkv, p_wqkvb, HID * QKV_N / 8);
    k_f2b<<<(NH * HD * HID / 8 + 255) / 256, 256>>>(Wo, p_wob, NH * HD * HID / 8);
    k_f2b<<<(NE * HID * 1024 / 8 + 255) / 256, 256>>>(Wgu, p_wgub, NE * HID * 1024 / 8);
    k_f2b<<<(NE * INTER * HID / 8 + 255) / 256, 256>>>(Wd, p_wdb, NE * INTER * HID / 8);

    // 1. pre-attn rmsnorm (bf16)
    k_rmsnorm<<<T_TOK, 256>>>(hidden, inln, nullptr, p_hb);
    // 2. qkv projection
    k_gemm_bb<<<dim3(QKV_N / BN, T_TOK / BM), 256>>>(p_hb, p_wqkvb, p_qkv, nullptr,
                                                     T_TOK, QKV_N, HID);
    // 3. per-head rmsnorm + rope + v convert
    k_qk_prep<<<dim3(NH + 2 * NKV, T_TOK), 32>>>(positions, qnw, knw);
    // 4. causal flash attention
    k_attn_mma<<<dim3(T_TOK / 64, NH), 128>>>();
    // 5. x = resid + attn @ Wo
    k_gemm_bb<<<dim3(HID / BN, T_TOK / BM), 256>>>(p_attnb, p_wob, out, hidden,
                                                   T_TOK, HID, NH * HD);
    // 6. post-attn rmsnorm
    k_rmsnorm<<<T_TOK, 256>>>(out, postln, p_h2, p_h2b);
    // 7-10. routing
    k_zero<<<1, 64>>>();
    k_route<<<T_TOK, 64>>>(p_h2, Wg);
    k_scan<<<1, 1>>>();
    k_scatter<<<T_TOK, 8>>>();
    // 11. grouped gate_up GEMM + fused activation
    k_moe1<<<dim3(8, 8, NE), 256>>>(p_h2b, p_wgub);
    // 12. grouped down GEMM, scatter-add into d_out
    k_moe2<<<dim3(HID / BN, 8, NE), 256>>>(p_wdb, out);
}